// round 1
// baseline (speedup 1.0000x reference)
#include <cuda_runtime.h>
#include <math.h>

#define H 128
#define DS 64
#define TCH 128
#define MAXN 20000
#define MAXNC 157

// ---------------- scratch (device globals; no allocations allowed) ----------------
__device__ float g_mi[MAXN * H];
__device__ float g_agg[MAXN * H];
__device__ float g_h1[MAXN * H];
__device__ float g_x[MAXN * H];
__device__ float g_z[MAXN * H];
__device__ float g_xs[MAXN * H];
__device__ float g_delta[MAXN * H];
__device__ float g_Bm[MAXN * DS];
__device__ float g_Cm[MAXN * DS];
__device__ float g_y[MAXN * H];
__device__ float g_M[H * H];              // x_proj_w[:, :8] @ dt_w
__device__ float g_aprod[MAXNC * H * DS];
__device__ float g_bstate[MAXNC * H * DS];
__device__ float g_sstart[MAXNC * H * DS];
__device__ int   g_is64;

// ---------------- helpers ----------------
__device__ __forceinline__ float sigm(float v) { return 1.f / (1.f + __expf(-v)); }
__device__ __forceinline__ float silu(float v) { return v / (1.f + __expf(-v)); }
__device__ __forceinline__ float softplus(float v) { return (v > 20.f) ? v : log1pf(__expf(v)); }

__device__ __forceinline__ unsigned long long pk2(float a, float b) {
    unsigned long long r;
    asm("mov.b64 %0, {%1,%2};" : "=l"(r) : "f"(a), "f"(b));
    return r;
}
__device__ __forceinline__ void upk2(unsigned long long v, float& a, float& b) {
    asm("mov.b64 {%0,%1}, %2;" : "=f"(a), "=f"(b) : "l"(v));
}
// Blackwell packed fp32 FMA: 2 MACs per instruction
__device__ __forceinline__ void fma2(unsigned long long& d, unsigned long long a, unsigned long long b) {
    asm("fma.rn.f32x2 %0, %1, %2, %0;" : "+l"(d) : "l"(a), "l"(b));
}

// shared tile layout (dynamic smem, ~59KB)
struct SmemG {
    float At[64][36];    // A chunk  (pad 36: conflict-free, float4-aligned)
    float Wt[32][128];   // weight chunk
    float T1[64][132];   // stage output tile
    int   rs[64];
    int   cs[64];
    float ea[64][2];
};

__device__ __forceinline__ void load_w_chunk(float* wt, const float* __restrict__ src, int tid) {
    #pragma unroll
    for (int j = 0; j < 4; j++) {
        int li = j * 1024 + tid * 4;
        *(float4*)&wt[li] = *(const float4*)(src + li);
    }
}
__device__ __forceinline__ void load_w_chunk_strided(float* wt, const float* __restrict__ base, int ldg, int tid) {
    #pragma unroll
    for (int j = 0; j < 4; j++) {
        int li = j * 1024 + tid * 4;
        int row = li >> 7, col = li & 127;
        *(float4*)&wt[li] = *(const float4*)(base + row * ldg + col);
    }
}

// 32-step K-chunk: 4 rows x 8 cols per thread, via f32x2
__device__ __forceinline__ void gemm_chunk(unsigned long long (&acc)[4][4],
                                           const float* a0r, const float* a1r,
                                           const float* a2r, const float* a3r,
                                           const float* wt, int n0) {
    #pragma unroll
    for (int k = 0; k < 32; k++) {
        const float* wr = wt + k * 128 + n0;
        unsigned long long b0 = *(const unsigned long long*)(wr + 0);
        unsigned long long b1 = *(const unsigned long long*)(wr + 2);
        unsigned long long b2 = *(const unsigned long long*)(wr + 4);
        unsigned long long b3 = *(const unsigned long long*)(wr + 6);
        unsigned long long p0 = pk2(a0r[k], a0r[k]);
        unsigned long long p1 = pk2(a1r[k], a1r[k]);
        unsigned long long p2 = pk2(a2r[k], a2r[k]);
        unsigned long long p3 = pk2(a3r[k], a3r[k]);
        fma2(acc[0][0], p0, b0); fma2(acc[0][1], p0, b1); fma2(acc[0][2], p0, b2); fma2(acc[0][3], p0, b3);
        fma2(acc[1][0], p1, b0); fma2(acc[1][1], p1, b1); fma2(acc[1][2], p1, b2); fma2(acc[1][3], p1, b3);
        fma2(acc[2][0], p2, b0); fma2(acc[2][1], p2, b1); fma2(acc[2][2], p2, b2); fma2(acc[2][3], p2, b3);
        fma2(acc[3][0], p3, b0); fma2(acc[3][1], p3, b1); fma2(acc[3][2], p3, b2); fma2(acc[3][3], p3, b3);
    }
}

// ---------------- kernels ----------------
__global__ void k_detect(const int* __restrict__ p) {
    if (threadIdx.x == 0) {
        int nz = 0;
        for (int i = 1; i < 128; i += 2) nz += (p[i] != 0);
        g_is64 = (nz == 0) ? 1 : 0;
    }
}

__global__ void k_zero(int n) {
    for (int i = blockIdx.x * blockDim.x + threadIdx.x; i < n; i += gridDim.x * blockDim.x) {
        g_mi[i] = 0.f;
        g_agg[i] = 0.f;
    }
}

__global__ void k_premat(const float* __restrict__ xpw, const float* __restrict__ dtw) {
    int o = blockIdx.x * blockDim.x + threadIdx.x;
    int i = o >> 7, j = o & 127;
    float s = 0.f;
    #pragma unroll
    for (int r = 0; r < 8; r++) s += xpw[i * 136 + r] * dtw[r * 128 + j];
    g_M[o] = s;
}

// Edge kernel: eo=[h[row],h[col],ea] -> silu(.@W1+b1) -> silu(.@W2+b2)=mij
// eij=sigmoid(mij.infw+infb); atomic scatter mij->agg[row], mij*eij->mi[col]
__global__ __launch_bounds__(256) void k_edge(
    const float* __restrict__ h, const void* __restrict__ eidx,
    const float* __restrict__ eattr,
    const float* __restrict__ W1, const float* __restrict__ b1,
    const float* __restrict__ W2, const float* __restrict__ b2,
    const float* __restrict__ infw, const float* __restrict__ infb, int E) {
    extern __shared__ char sraw[];
    SmemG& S = *(SmemG*)sraw;
    int tid = threadIdx.x;
    int e0 = blockIdx.x * 64;
    int is64 = g_is64;
    if (tid < 64) {
        int e = min(e0 + tid, E - 1);
        if (is64) {
            const long long* q = (const long long*)eidx;
            S.rs[tid] = (int)q[e];
            S.cs[tid] = (int)q[(size_t)E + e];
        } else {
            const int* q = (const int*)eidx;
            S.rs[tid] = q[e];
            S.cs[tid] = q[E + e];
        }
        S.ea[tid][0] = eattr[2 * e];
        S.ea[tid][1] = eattr[2 * e + 1];
    }
    __syncthreads();
    int tx = tid & 15, ty = tid >> 4;
    int n0 = tx * 8, r0 = ty * 4;
    int le = tid >> 2, lk = (tid & 3) * 8;
    unsigned long long acc[4][4] = {};

    // stage 1: K = 256 (h[row] | h[col]), edge_attr epilogue
    for (int kc = 0; kc < 256; kc += 32) {
        int idx = (kc < 128) ? S.rs[le] : S.cs[le];
        const float* src = h + (size_t)idx * H + (kc & 127) + lk;
        *(float4*)&S.At[le][lk]     = *(const float4*)src;
        *(float4*)&S.At[le][lk + 4] = *(const float4*)(src + 4);
        load_w_chunk(&S.Wt[0][0], W1 + kc * H, tid);
        __syncthreads();
        gemm_chunk(acc, &S.At[r0][0], &S.At[r0 + 1][0], &S.At[r0 + 2][0], &S.At[r0 + 3][0], &S.Wt[0][0], n0);
        __syncthreads();
    }
    #pragma unroll
    for (int i = 0; i < 4; i++) {
        float ea0 = S.ea[r0 + i][0], ea1 = S.ea[r0 + i][1];
        #pragma unroll
        for (int j = 0; j < 4; j++) {
            float v0, v1;
            upk2(acc[i][j], v0, v1);
            int n = n0 + 2 * j;
            v0 += ea0 * W1[256 * H + n]     + ea1 * W1[257 * H + n]     + b1[n];
            v1 += ea0 * W1[256 * H + n + 1] + ea1 * W1[257 * H + n + 1] + b1[n + 1];
            S.T1[r0 + i][n]     = silu(v0);
            S.T1[r0 + i][n + 1] = silu(v1);
        }
    }
    __syncthreads();

    // stage 2: K = 128 with W2
    #pragma unroll
    for (int i = 0; i < 4; i++)
        #pragma unroll
        for (int j = 0; j < 4; j++) acc[i][j] = 0ull;
    for (int kc = 0; kc < 128; kc += 32) {
        load_w_chunk(&S.Wt[0][0], W2 + kc * H, tid);
        __syncthreads();
        gemm_chunk(acc, &S.T1[r0][kc], &S.T1[r0 + 1][kc], &S.T1[r0 + 2][kc], &S.T1[r0 + 3][kc], &S.Wt[0][0], n0);
        __syncthreads();
    }
    float mv[4][8];
    #pragma unroll
    for (int i = 0; i < 4; i++) {
        #pragma unroll
        for (int j = 0; j < 4; j++) {
            float v0, v1;
            upk2(acc[i][j], v0, v1);
            int n = n0 + 2 * j;
            mv[i][2 * j]     = silu(v0 + b2[n]);
            mv[i][2 * j + 1] = silu(v1 + b2[n + 1]);
        }
    }
    // infiltration gate: per-edge dot(mij, infw), reduce over 16 threads sharing the edge
    float einf[4];
    #pragma unroll
    for (int i = 0; i < 4; i++) {
        float p = 0.f;
        #pragma unroll
        for (int jj = 0; jj < 8; jj++) p += mv[i][jj] * infw[n0 + jj];
        #pragma unroll
        for (int off = 8; off; off >>= 1) p += __shfl_down_sync(0xffffffffu, p, off, 16);
        p = __shfl_sync(0xffffffffu, p, 0, 16);
        einf[i] = sigm(p + infb[0]);
    }
    // scatter
    #pragma unroll
    for (int i = 0; i < 4; i++) {
        if (e0 + r0 + i >= E) break;
        int er = S.rs[r0 + i], ec = S.cs[r0 + i];
        float g = einf[i];
        float* pa = g_agg + (size_t)er * H + n0;
        float* pm = g_mi + (size_t)ec * H + n0;
        #pragma unroll
        for (int jj = 0; jj < 8; jj++) {
            atomicAdd(pa + jj, mv[i][jj]);
            atomicAdd(pm + jj, mv[i][jj] * g);
        }
    }
}

// h1 = h + nodeMLP([h, agg])
__global__ __launch_bounds__(256) void k_node1(
    const float* __restrict__ h,
    const float* __restrict__ W1, const float* __restrict__ b1v,
    const float* __restrict__ W2, const float* __restrict__ b2v, int Nn) {
    extern __shared__ char sraw[];
    SmemG& S = *(SmemG*)sraw;
    int tid = threadIdx.x;
    int row0 = blockIdx.x * 64;
    int tx = tid & 15, ty = tid >> 4;
    int n0 = tx * 8, r0 = ty * 4;
    int le = tid >> 2, lk = (tid & 3) * 8;
    int node_l = min(row0 + le, Nn - 1);
    unsigned long long acc[4][4] = {};
    for (int kc = 0; kc < 256; kc += 32) {
        const float* srcb = (kc < 128) ? h : g_agg;
        const float* src = srcb + (size_t)node_l * H + (kc & 127) + lk;
        *(float4*)&S.At[le][lk]     = *(const float4*)src;
        *(float4*)&S.At[le][lk + 4] = *(const float4*)(src + 4);
        load_w_chunk(&S.Wt[0][0], W1 + kc * H, tid);
        __syncthreads();
        gemm_chunk(acc, &S.At[r0][0], &S.At[r0 + 1][0], &S.At[r0 + 2][0], &S.At[r0 + 3][0], &S.Wt[0][0], n0);
        __syncthreads();
    }
    #pragma unroll
    for (int i = 0; i < 4; i++)
        #pragma unroll
        for (int j = 0; j < 4; j++) {
            float v0, v1;
            upk2(acc[i][j], v0, v1);
            int n = n0 + 2 * j;
            S.T1[r0 + i][n]     = silu(v0 + b1v[n]);
            S.T1[r0 + i][n + 1] = silu(v1 + b1v[n + 1]);
            acc[i][j] = 0ull;
        }
    __syncthreads();
    for (int kc = 0; kc < 128; kc += 32) {
        load_w_chunk(&S.Wt[0][0], W2 + kc * H, tid);
        __syncthreads();
        gemm_chunk(acc, &S.T1[r0][kc], &S.T1[r0 + 1][kc], &S.T1[r0 + 2][kc], &S.T1[r0 + 3][kc], &S.Wt[0][0], n0);
        __syncthreads();
    }
    #pragma unroll
    for (int i = 0; i < 4; i++) {
        int node = row0 + r0 + i;
        if (node < Nn) {
            #pragma unroll
            for (int j = 0; j < 4; j++) {
                float v0, v1;
                upk2(acc[i][j], v0, v1);
                int n = n0 + 2 * j;
                g_h1[(size_t)node * H + n]     = v0 + b2v[n]     + h[(size_t)node * H + n];
                g_h1[(size_t)node * H + n + 1] = v1 + b2v[n + 1] + h[(size_t)node * H + n + 1];
            }
        }
    }
}

// h2 = nodeMLP([mi, h1]);  xz = h2 @ in_proj_w ; split into g_x, g_z
__global__ __launch_bounds__(256) void k_node2(
    const float* __restrict__ W1, const float* __restrict__ b1v,
    const float* __restrict__ W2, const float* __restrict__ b2v,
    const float* __restrict__ inpw, int Nn) {
    extern __shared__ char sraw[];
    SmemG& S = *(SmemG*)sraw;
    int tid = threadIdx.x;
    int row0 = blockIdx.x * 64;
    int tx = tid & 15, ty = tid >> 4;
    int n0 = tx * 8, r0 = ty * 4;
    int le = tid >> 2, lk = (tid & 3) * 8;
    int node_l = min(row0 + le, Nn - 1);
    unsigned long long acc[4][4] = {};
    for (int kc = 0; kc < 256; kc += 32) {
        const float* srcb = (kc < 128) ? g_mi : g_h1;
        const float* src = srcb + (size_t)node_l * H + (kc & 127) + lk;
        *(float4*)&S.At[le][lk]     = *(const float4*)src;
        *(float4*)&S.At[le][lk + 4] = *(const float4*)(src + 4);
        load_w_chunk(&S.Wt[0][0], W1 + kc * H, tid);
        __syncthreads();
        gemm_chunk(acc, &S.At[r0][0], &S.At[r0 + 1][0], &S.At[r0 + 2][0], &S.At[r0 + 3][0], &S.Wt[0][0], n0);
        __syncthreads();
    }
    #pragma unroll
    for (int i = 0; i < 4; i++)
        #pragma unroll
        for (int j = 0; j < 4; j++) {
            float v0, v1;
            upk2(acc[i][j], v0, v1);
            int n = n0 + 2 * j;
            S.T1[r0 + i][n]     = silu(v0 + b1v[n]);
            S.T1[r0 + i][n + 1] = silu(v1 + b1v[n + 1]);
            acc[i][j] = 0ull;
        }
    __syncthreads();
    for (int kc = 0; kc < 128; kc += 32) {
        load_w_chunk(&S.Wt[0][0], W2 + kc * H, tid);
        __syncthreads();
        gemm_chunk(acc, &S.T1[r0][kc], &S.T1[r0 + 1][kc], &S.T1[r0 + 2][kc], &S.T1[r0 + 3][kc], &S.Wt[0][0], n0);
        __syncthreads();
    }
    // h2 tile (with b2, no activation) back into T1
    float h2v[4][8];
    #pragma unroll
    for (int i = 0; i < 4; i++)
        #pragma unroll
        for (int j = 0; j < 4; j++) {
            float v0, v1;
            upk2(acc[i][j], v0, v1);
            int n = n0 + 2 * j;
            h2v[i][2 * j] = v0 + b2v[n];
            h2v[i][2 * j + 1] = v1 + b2v[n + 1];
        }
    __syncthreads();
    #pragma unroll
    for (int i = 0; i < 4; i++)
        #pragma unroll
        for (int jj = 0; jj < 8; jj++) S.T1[r0 + i][n0 + jj] = h2v[i][jj];
    __syncthreads();
    // stage 3: xz = h2 @ in_proj_w (two 128-col halves)
    for (int half = 0; half < 2; half++) {
        #pragma unroll
        for (int i = 0; i < 4; i++)
            #pragma unroll
            for (int j = 0; j < 4; j++) acc[i][j] = 0ull;
        for (int kc = 0; kc < 128; kc += 32) {
            load_w_chunk_strided(&S.Wt[0][0], inpw + kc * 256 + half * 128, 256, tid);
            __syncthreads();
            gemm_chunk(acc, &S.T1[r0][kc], &S.T1[r0 + 1][kc], &S.T1[r0 + 2][kc], &S.T1[r0 + 3][kc], &S.Wt[0][0], n0);
            __syncthreads();
        }
        float* dst = half ? g_z : g_x;
        #pragma unroll
        for (int i = 0; i < 4; i++) {
            int node = row0 + r0 + i;
            if (node < Nn) {
                #pragma unroll
                for (int j = 0; j < 4; j++) {
                    float v0, v1;
                    upk2(acc[i][j], v0, v1);
                    int n = n0 + 2 * j;
                    dst[(size_t)node * H + n] = v0;
                    dst[(size_t)node * H + n + 1] = v1;
                }
            }
        }
    }
}

// conv + silu -> xs ; B,C = xs @ x_proj_w[:,8:136] ; delta = softplus(xs @ M + dt_b)
__global__ __launch_bounds__(256) void k_conv_proj(
    const float* __restrict__ xpw, const float* __restrict__ convw,
    const float* __restrict__ convb, const float* __restrict__ dtb, int Nn) {
    extern __shared__ char sraw[];
    SmemG& S = *(SmemG*)sraw;
    int tid = threadIdx.x;
    int row0 = blockIdx.x * 64;
    int tx = tid & 15, ty = tid >> 4;
    int n0 = tx * 8, r0 = ty * 4;
    // stage A: causal depthwise conv (DC=4) + silu
    for (int it = 0; it < 32; ++it) {
        int lin = it * 256 + tid;
        int r = lin >> 7, c = lin & 127;
        int node = row0 + r;
        float v = 0.f;
        if (node < Nn) {
            float a = convb[c];
            #pragma unroll
            for (int k = 0; k < 4; k++) {
                int t = node - 3 + k;
                if (t >= 0) a += convw[k * H + c] * g_x[(size_t)t * H + c];
            }
            v = silu(a);
            g_xs[(size_t)node * H + c] = v;
        }
        S.T1[r][c] = v;
    }
    __syncthreads();
    // stage B1: [B|C] = xs @ xpw[:, 8:136]
    unsigned long long acc[4][4] = {};
    for (int kc = 0; kc < 128; kc += 32) {
        load_w_chunk_strided(&S.Wt[0][0], xpw + kc * 136 + 8, 136, tid);
        __syncthreads();
        gemm_chunk(acc, &S.T1[r0][kc], &S.T1[r0 + 1][kc], &S.T1[r0 + 2][kc], &S.T1[r0 + 3][kc], &S.Wt[0][0], n0);
        __syncthreads();
    }
    #pragma unroll
    for (int i = 0; i < 4; i++) {
        int node = row0 + r0 + i;
        if (node < Nn) {
            #pragma unroll
            for (int j = 0; j < 4; j++) {
                float v0, v1;
                upk2(acc[i][j], v0, v1);
                int n = n0 + 2 * j;
                if (n < 64) {
                    g_Bm[(size_t)node * DS + n] = v0;
                    g_Bm[(size_t)node * DS + n + 1] = v1;
                } else {
                    g_Cm[(size_t)node * DS + n - 64] = v0;
                    g_Cm[(size_t)node * DS + n - 63] = v1;
                }
            }
        }
        #pragma unroll
        for (int j = 0; j < 4; j++) acc[i][j] = 0ull;
    }
    // stage B2: delta = softplus(xs @ M + dt_b)
    for (int kc = 0; kc < 128; kc += 32) {
        load_w_chunk(&S.Wt[0][0], g_M + kc * H, tid);
        __syncthreads();
        gemm_chunk(acc, &S.T1[r0][kc], &S.T1[r0 + 1][kc], &S.T1[r0 + 2][kc], &S.T1[r0 + 3][kc], &S.Wt[0][0], n0);
        __syncthreads();
    }
    #pragma unroll
    for (int i = 0; i < 4; i++) {
        int node = row0 + r0 + i;
        if (node < Nn) {
            #pragma unroll
            for (int j = 0; j < 4; j++) {
                float v0, v1;
                upk2(acc[i][j], v0, v1);
                int n = n0 + 2 * j;
                g_delta[(size_t)node * H + n] = softplus(v0 + dtb[n]);
                g_delta[(size_t)node * H + n + 1] = softplus(v1 + dtb[n + 1]);
            }
        }
    }
}

// chunked selective scan, phase A: local scans per chunk
__global__ void k_scanA(const float* __restrict__ A_log, int Nn) {
    int warp = threadIdx.x >> 5;
    int lane = threadIdx.x & 31;
    int c = blockIdx.x;
    int hch = blockIdx.y * 8 + warp;
    int s0 = lane, s1 = lane + 32;
    float A0 = -__expf(A_log[hch * DS + s0]);
    float A1 = -__expf(A_log[hch * DS + s1]);
    float hc0 = 0.f, hc1 = 0.f, dsum = 0.f;
    int t0 = c * TCH, t1 = min(Nn, t0 + TCH);
    for (int t = t0; t < t1; ++t) {
        float d = __ldg(&g_delta[(size_t)t * H + hch]);
        float xv = __ldg(&g_xs[(size_t)t * H + hch]);
        float b0 = g_Bm[(size_t)t * DS + s0];
        float b1v = g_Bm[(size_t)t * DS + s1];
        float dx = d * xv;
        hc0 = __expf(d * A0) * hc0 + dx * b0;
        hc1 = __expf(d * A1) * hc1 + dx * b1v;
        dsum += d;
    }
    size_t o = ((size_t)c * H + hch) * DS;
    g_bstate[o + s0] = hc0;
    g_bstate[o + s1] = hc1;
    g_aprod[o + s0] = __expf(A0 * dsum);
    g_aprod[o + s1] = __expf(A1 * dsum);
}

// phase B: sequential prefix over chunks (8192 independent lanes)
__global__ void k_prefix(int NC) {
    int hs = blockIdx.x * blockDim.x + threadIdx.x;  // 0..8191
    float st = 0.f;
    for (int c = 0; c < NC; c++) {
        size_t o = (size_t)c * (H * DS) + hs;
        g_sstart[o] = st;
        st = g_aprod[o] * st + g_bstate[o];
    }
}

// phase C: recompute within chunk, produce y (with +D*x and silu(z) gate)
__global__ void k_scanC(const float* __restrict__ A_log, const float* __restrict__ Dv, int Nn) {
    int warp = threadIdx.x >> 5;
    int lane = threadIdx.x & 31;
    int c = blockIdx.x;
    int hch = blockIdx.y * 8 + warp;
    int s0 = lane, s1 = lane + 32;
    float A0 = -__expf(A_log[hch * DS + s0]);
    float A1 = -__expf(A_log[hch * DS + s1]);
    size_t o = ((size_t)c * H + hch) * DS;
    float hc0 = g_sstart[o + s0];
    float hc1 = g_sstart[o + s1];
    float dh = Dv[hch];
    int t0 = c * TCH, t1 = min(Nn, t0 + TCH);
    for (int t = t0; t < t1; ++t) {
        float d = __ldg(&g_delta[(size_t)t * H + hch]);
        float xv = __ldg(&g_xs[(size_t)t * H + hch]);
        float b0 = g_Bm[(size_t)t * DS + s0];
        float b1v = g_Bm[(size_t)t * DS + s1];
        float c0 = g_Cm[(size_t)t * DS + s0];
        float c1 = g_Cm[(size_t)t * DS + s1];
        float dx = d * xv;
        hc0 = __expf(d * A0) * hc0 + dx * b0;
        hc1 = __expf(d * A1) * hc1 + dx * b1v;
        float p = hc0 * c0 + hc1 * c1;
        #pragma unroll
        for (int off = 16; off; off >>= 1) p += __shfl_down_sync(0xffffffffu, p, off);
        if (lane == 0) {
            float zv = g_z[(size_t)t * H + hch];
            g_y[(size_t)t * H + hch] = (p + dh * xv) * zv * sigm(zv);
        }
    }
}

// out = y @ out_proj_w
__global__ __launch_bounds__(256) void k_out(const float* __restrict__ W, float* __restrict__ out, int Nn) {
    extern __shared__ char sraw[];
    SmemG& S = *(SmemG*)sraw;
    int tid = threadIdx.x;
    int row0 = blockIdx.x * 64;
    int tx = tid & 15, ty = tid >> 4;
    int n0 = tx * 8, r0 = ty * 4;
    for (int it = 0; it < 32; ++it) {
        int lin = it * 256 + tid;
        int r = lin >> 7, c = lin & 127;
        int node = min(row0 + r, Nn - 1);
        S.T1[r][c] = g_y[(size_t)node * H + c];
    }
    __syncthreads();
    unsigned long long acc[4][4] = {};
    for (int kc = 0; kc < 128; kc += 32) {
        load_w_chunk(&S.Wt[0][0], W + kc * H, tid);
        __syncthreads();
        gemm_chunk(acc, &S.T1[r0][kc], &S.T1[r0 + 1][kc], &S.T1[r0 + 2][kc], &S.T1[r0 + 3][kc], &S.Wt[0][0], n0);
        __syncthreads();
    }
    #pragma unroll
    for (int i = 0; i < 4; i++) {
        int node = row0 + r0 + i;
        if (node < Nn) {
            #pragma unroll
            for (int j = 0; j < 4; j++) {
                float v0, v1;
                upk2(acc[i][j], v0, v1);
                int n = n0 + 2 * j;
                out[(size_t)node * H + n] = v0;
                out[(size_t)node * H + n + 1] = v1;
            }
        }
    }
}

// ---------------- launch ----------------
extern "C" void kernel_launch(void* const* d_in, const int* in_sizes, int n_in,
                              void* d_out, int out_size) {
    const float* h      = (const float*)d_in[0];
    const void*  eidx   = d_in[1];
    const float* eattr  = (const float*)d_in[2];
    const float* e_w1   = (const float*)d_in[3];
    const float* e_b1   = (const float*)d_in[4];
    const float* e_w2   = (const float*)d_in[5];
    const float* e_b2   = (const float*)d_in[6];
    const float* inf_w  = (const float*)d_in[7];
    const float* inf_b  = (const float*)d_in[8];
    const float* n_w1   = (const float*)d_in[9];
    const float* n_b1   = (const float*)d_in[10];
    const float* n_w2   = (const float*)d_in[11];
    const float* n_b2   = (const float*)d_in[12];
    const float* in_prj = (const float*)d_in[13];
    const float* conv_w = (const float*)d_in[14];
    const float* conv_b = (const float*)d_in[15];
    const float* x_proj = (const float*)d_in[16];
    const float* dt_w   = (const float*)d_in[17];
    const float* dt_b   = (const float*)d_in[18];
    const float* A_log  = (const float*)d_in[19];
    const float* Dv     = (const float*)d_in[20];
    const float* out_w  = (const float*)d_in[21];

    int Nn = in_sizes[0] / H;
    int E  = in_sizes[2] / 2;
    int NC = (Nn + TCH - 1) / TCH;
    int nb = (Nn + 63) / 64;
    int smem = (int)sizeof(SmemG);

    cudaFuncSetAttribute(k_edge,      cudaFuncAttributeMaxDynamicSharedMemorySize, smem);
    cudaFuncSetAttribute(k_node1,     cudaFuncAttributeMaxDynamicSharedMemorySize, smem);
    cudaFuncSetAttribute(k_node2,     cudaFuncAttributeMaxDynamicSharedMemorySize, smem);
    cudaFuncSetAttribute(k_conv_proj, cudaFuncAttributeMaxDynamicSharedMemorySize, smem);
    cudaFuncSetAttribute(k_out,       cudaFuncAttributeMaxDynamicSharedMemorySize, smem);

    k_detect<<<1, 32>>>((const int*)eidx);
    k_zero<<<256, 256>>>(Nn * H);
    k_premat<<<64, 256>>>(x_proj, dt_w);
    k_edge<<<(E + 63) / 64, 256, smem>>>(h, eidx, eattr, e_w1, e_b1, e_w2, e_b2, inf_w, inf_b, E);
    k_node1<<<nb, 256, smem>>>(h, n_w1, n_b1, n_w2, n_b2, Nn);
    k_node2<<<nb, 256, smem>>>(n_w1, n_b1, n_w2, n_b2, in_prj, Nn);
    k_conv_proj<<<nb, 256, smem>>>(x_proj, conv_w, conv_b, dt_b, Nn);
    dim3 gs(NC, 16);
    k_scanA<<<gs, 256>>>(A_log, Nn);
    k_prefix<<<32, 256>>>(NC);
    k_scanC<<<gs, 256>>>(A_log, Dv, Nn);
    k_out<<<nb, 256, smem>>>(out_w, (float*)d_out, Nn);
}

// round 2
// speedup vs baseline: 1.6350x; 1.6350x over previous
#include <cuda_runtime.h>
#include <math.h>

#define H 128
#define DS 64
#define TCH 128
#define MAXN 20000
#define MAXNC 157

typedef unsigned long long ull;

// ---------------- scratch (device globals; no allocations allowed) ----------------
__device__ float g_mi[MAXN * H];
__device__ float g_agg[MAXN * H];
__device__ float g_h1[MAXN * H];
__device__ float g_x[MAXN * H];
__device__ float g_z[MAXN * H];
__device__ float g_xs[MAXN * H];
__device__ float g_delta[MAXN * H];
__device__ float g_Bm[MAXN * DS];
__device__ float g_Cm[MAXN * DS];
__device__ float g_y[MAXN * H];
__device__ float g_P[MAXN * H];          // h @ W1a
__device__ float g_Q[MAXN * H];          // h @ W1b
__device__ float g_M[H * H];             // x_proj_w[:, :8] @ dt_w
__device__ float g_aprod[MAXNC * H * DS];
__device__ float g_bstate[MAXNC * H * DS];
__device__ float g_sstart[MAXNC * H * DS];
__device__ int   g_is64;

// ---------------- helpers ----------------
__device__ __forceinline__ float sigm(float v) { return 1.f / (1.f + __expf(-v)); }
__device__ __forceinline__ float silu(float v) { return v / (1.f + __expf(-v)); }
__device__ __forceinline__ float softplus(float v) { return (v > 20.f) ? v : log1pf(__expf(v)); }

__device__ __forceinline__ ull pk2(float a, float b) {
    ull r;
    asm("mov.b64 %0, {%1,%2};" : "=l"(r) : "f"(a), "f"(b));
    return r;
}
__device__ __forceinline__ void upk2(ull v, float& a, float& b) {
    asm("mov.b64 {%0,%1}, %2;" : "=f"(a), "=f"(b) : "l"(v));
}
// Blackwell packed fp32 FMA: 2 MACs per instruction
__device__ __forceinline__ void fma2(ull& d, ull a, ull b) {
    asm("fma.rn.f32x2 %0, %1, %2, %0;" : "+l"(d) : "l"(a), "l"(b));
}

// shared tile layout for node-style kernels (~59KB)
struct SmemG {
    float At[64][36];    // A chunk  (pad: 144B row stride, 16B aligned)
    float Wt[32][128];   // weight chunk
    float T1[64][132];   // stage output tile (528B row stride)
    int   rs[64];
    int   cs[64];
    float ea[64][2];
};

// shared tile layout for edge kernel (~53KB)
struct SmemE {
    float T1[64][132];
    float Wt[32][128];
    int   rs[64];
    int   cs[64];
    float ea[64][2];
    float wc0[128];
    float wc1[128];
    float b1s[128];
};

__device__ __forceinline__ void load_w_chunk(float* wt, const float* __restrict__ src, int tid) {
    #pragma unroll
    for (int j = 0; j < 4; j++) {
        int li = j * 1024 + tid * 4;
        *(float4*)&wt[li] = *(const float4*)(src + li);
    }
}
__device__ __forceinline__ void load_w_chunk_strided(float* wt, const float* __restrict__ base, int ldg, int tid) {
    #pragma unroll
    for (int j = 0; j < 4; j++) {
        int li = j * 1024 + tid * 4;
        int row = li >> 7, col = li & 127;
        *(float4*)&wt[li] = *(const float4*)(base + row * ldg + col);
    }
}

// 32-step K-chunk: 4 rows x 8 cols per thread. A via LDS.128, B via packed 16B loads.
__device__ __forceinline__ void gemm_chunk(ull (&acc)[4][4],
                                           const float* a0, const float* a1,
                                           const float* a2, const float* a3,
                                           const float* wt, int n0) {
    #pragma unroll
    for (int kk = 0; kk < 32; kk += 4) {
        float4 A0 = *(const float4*)(a0 + kk);
        float4 A1 = *(const float4*)(a1 + kk);
        float4 A2 = *(const float4*)(a2 + kk);
        float4 A3 = *(const float4*)(a3 + kk);
        const float* w = wt + kk * 128 + n0;
        #pragma unroll
        for (int k4 = 0; k4 < 4; k4++) {
            ulonglong2 bA = *(const ulonglong2*)(w + k4 * 128);
            ulonglong2 bB = *(const ulonglong2*)(w + k4 * 128 + 4);
            float fa0 = (&A0.x)[k4], fa1 = (&A1.x)[k4];
            float fa2 = (&A2.x)[k4], fa3 = (&A3.x)[k4];
            ull p0 = pk2(fa0, fa0), p1 = pk2(fa1, fa1);
            ull p2 = pk2(fa2, fa2), p3 = pk2(fa3, fa3);
            fma2(acc[0][0], p0, bA.x); fma2(acc[0][1], p0, bA.y); fma2(acc[0][2], p0, bB.x); fma2(acc[0][3], p0, bB.y);
            fma2(acc[1][0], p1, bA.x); fma2(acc[1][1], p1, bA.y); fma2(acc[1][2], p1, bB.x); fma2(acc[1][3], p1, bB.y);
            fma2(acc[2][0], p2, bA.x); fma2(acc[2][1], p2, bA.y); fma2(acc[2][2], p2, bB.x); fma2(acc[2][3], p2, bB.y);
            fma2(acc[3][0], p3, bA.x); fma2(acc[3][1], p3, bA.y); fma2(acc[3][2], p3, bB.x); fma2(acc[3][3], p3, bB.y);
        }
    }
}

// ---------------- kernels ----------------
__global__ void k_detect(const int* __restrict__ p) {
    if (threadIdx.x == 0) {
        int nz = 0;
        for (int i = 1; i < 128; i += 2) nz += (p[i] != 0);
        g_is64 = (nz == 0) ? 1 : 0;
    }
}

__global__ void k_zero(int n) {
    for (int i = blockIdx.x * blockDim.x + threadIdx.x; i < n; i += gridDim.x * blockDim.x) {
        g_mi[i] = 0.f;
        g_agg[i] = 0.f;
    }
}

__global__ void k_premat(const float* __restrict__ xpw, const float* __restrict__ dtw) {
    int o = blockIdx.x * blockDim.x + threadIdx.x;
    int i = o >> 7, j = o & 127;
    float s = 0.f;
    #pragma unroll
    for (int r = 0; r < 8; r++) s += xpw[i * 136 + r] * dtw[r * 128 + j];
    g_M[o] = s;
}

// P = h @ W1[0:128], Q = h @ W1[128:256]
__global__ __launch_bounds__(256, 3) void k_pq(
    const float* __restrict__ h, const float* __restrict__ W1, int Nn) {
    extern __shared__ char sraw[];
    SmemG& S = *(SmemG*)sraw;
    int tid = threadIdx.x;
    int row0 = blockIdx.x * 64;
    int tx = tid & 15, ty = tid >> 4;
    int n0 = tx * 8, r0 = ty * 4;
    for (int it = 0; it < 32; ++it) {
        int lin = it * 256 + tid;
        int r = lin >> 7, c = lin & 127;
        int node = min(row0 + r, Nn - 1);
        S.T1[r][c] = h[(size_t)node * H + c];
    }
    __syncthreads();
    for (int tgt = 0; tgt < 2; tgt++) {
        ull acc[4][4] = {};
        for (int kc = 0; kc < 128; kc += 32) {
            load_w_chunk(&S.Wt[0][0], W1 + (tgt * 128 + kc) * H, tid);
            __syncthreads();
            gemm_chunk(acc, &S.T1[r0][kc], &S.T1[r0 + 1][kc], &S.T1[r0 + 2][kc], &S.T1[r0 + 3][kc], &S.Wt[0][0], n0);
            __syncthreads();
        }
        float* dst = tgt ? g_Q : g_P;
        #pragma unroll
        for (int i = 0; i < 4; i++) {
            int node = row0 + r0 + i;
            if (node < Nn) {
                #pragma unroll
                for (int j = 0; j < 4; j++) {
                    float v0, v1;
                    upk2(acc[i][j], v0, v1);
                    int n = n0 + 2 * j;
                    dst[(size_t)node * H + n] = v0;
                    dst[(size_t)node * H + n + 1] = v1;
                }
            }
        }
    }
}

// Edge kernel v2: pre1 = P[row]+Q[col]+ea@W1c+b1 -> silu -> @W2+b2 -> silu = mij
// eij=sigmoid(mij.infw+infb); scatter mij->agg[row], mij*eij->mi[col]
__global__ __launch_bounds__(256, 3) void k_edge(
    const void* __restrict__ eidx, const float* __restrict__ eattr,
    const float* __restrict__ W1, const float* __restrict__ b1,
    const float* __restrict__ W2, const float* __restrict__ b2,
    const float* __restrict__ infw, const float* __restrict__ infb, int E) {
    extern __shared__ char sraw[];
    SmemE& S = *(SmemE*)sraw;
    int tid = threadIdx.x;
    int e0 = blockIdx.x * 64;
    int is64 = g_is64;
    if (tid < 64) {
        int e = min(e0 + tid, E - 1);
        if (is64) {
            const long long* q = (const long long*)eidx;
            S.rs[tid] = (int)q[e];
            S.cs[tid] = (int)q[(size_t)E + e];
        } else {
            const int* q = (const int*)eidx;
            S.rs[tid] = q[e];
            S.cs[tid] = q[E + e];
        }
        S.ea[tid][0] = eattr[2 * e];
        S.ea[tid][1] = eattr[2 * e + 1];
    }
    if (tid < 128) {
        S.wc0[tid] = W1[256 * H + tid];
        S.wc1[tid] = W1[257 * H + tid];
        S.b1s[tid] = b1[tid];
    }
    __syncthreads();

    // stage A: gather P[row] + Q[col], add ea terms + b1, silu -> T1
    {
        int r_loc = tid >> 3;          // 0..31
        int c8 = tid & 7;
        #pragma unroll
        for (int half = 0; half < 2; half++) {
            int r = half * 32 + r_loc;
            const float* Pr = g_P + (size_t)S.rs[r] * H;
            const float* Qr = g_Q + (size_t)S.cs[r] * H;
            float ea0 = S.ea[r][0], ea1 = S.ea[r][1];
            #pragma unroll
            for (int i = 0; i < 4; i++) {
                int c = c8 * 4 + i * 32;
                float4 p = *(const float4*)(Pr + c);
                float4 q = *(const float4*)(Qr + c);
                #pragma unroll
                for (int j = 0; j < 4; j++) {
                    float v = (&p.x)[j] + (&q.x)[j]
                            + ea0 * S.wc0[c + j] + ea1 * S.wc1[c + j] + S.b1s[c + j];
                    S.T1[r][c + j] = silu(v);
                }
            }
        }
    }
    __syncthreads();

    // stage B: K = 128 with W2
    int tx = tid & 15, ty = tid >> 4;
    int n0 = tx * 8, r0 = ty * 4;
    ull acc[4][4] = {};
    for (int kc = 0; kc < 128; kc += 32) {
        load_w_chunk(&S.Wt[0][0], W2 + kc * H, tid);
        __syncthreads();
        gemm_chunk(acc, &S.T1[r0][kc], &S.T1[r0 + 1][kc], &S.T1[r0 + 2][kc], &S.T1[r0 + 3][kc], &S.Wt[0][0], n0);
        __syncthreads();
    }
    float mv[4][8];
    #pragma unroll
    for (int i = 0; i < 4; i++) {
        #pragma unroll
        for (int j = 0; j < 4; j++) {
            float v0, v1;
            upk2(acc[i][j], v0, v1);
            int n = n0 + 2 * j;
            mv[i][2 * j]     = silu(v0 + b2[n]);
            mv[i][2 * j + 1] = silu(v1 + b2[n + 1]);
        }
    }
    // infiltration gate: per-edge dot(mij, infw), reduce over 16 threads sharing the edge
    float einf[4];
    #pragma unroll
    for (int i = 0; i < 4; i++) {
        float p = 0.f;
        #pragma unroll
        for (int jj = 0; jj < 8; jj++) p += mv[i][jj] * infw[n0 + jj];
        #pragma unroll
        for (int off = 8; off; off >>= 1) p += __shfl_down_sync(0xffffffffu, p, off, 16);
        p = __shfl_sync(0xffffffffu, p, 0, 16);
        einf[i] = sigm(p + infb[0]);
    }
    // scatter
    #pragma unroll
    for (int i = 0; i < 4; i++) {
        if (e0 + r0 + i >= E) break;
        int er = S.rs[r0 + i], ec = S.cs[r0 + i];
        float g = einf[i];
        float* pa = g_agg + (size_t)er * H + n0;
        float* pm = g_mi + (size_t)ec * H + n0;
        #pragma unroll
        for (int jj = 0; jj < 8; jj++) {
            atomicAdd(pa + jj, mv[i][jj]);
            atomicAdd(pm + jj, mv[i][jj] * g);
        }
    }
}

// h1 = h + nodeMLP([h, agg])
__global__ __launch_bounds__(256, 3) void k_node1(
    const float* __restrict__ h,
    const float* __restrict__ W1, const float* __restrict__ b1v,
    const float* __restrict__ W2, const float* __restrict__ b2v, int Nn) {
    extern __shared__ char sraw[];
    SmemG& S = *(SmemG*)sraw;
    int tid = threadIdx.x;
    int row0 = blockIdx.x * 64;
    int tx = tid & 15, ty = tid >> 4;
    int n0 = tx * 8, r0 = ty * 4;
    int le = tid >> 2, lk = (tid & 3) * 8;
    int node_l = min(row0 + le, Nn - 1);
    ull acc[4][4] = {};
    for (int kc = 0; kc < 256; kc += 32) {
        const float* srcb = (kc < 128) ? h : g_agg;
        const float* src = srcb + (size_t)node_l * H + (kc & 127) + lk;
        *(float4*)&S.At[le][lk]     = *(const float4*)src;
        *(float4*)&S.At[le][lk + 4] = *(const float4*)(src + 4);
        load_w_chunk(&S.Wt[0][0], W1 + kc * H, tid);
        __syncthreads();
        gemm_chunk(acc, &S.At[r0][0], &S.At[r0 + 1][0], &S.At[r0 + 2][0], &S.At[r0 + 3][0], &S.Wt[0][0], n0);
        __syncthreads();
    }
    #pragma unroll
    for (int i = 0; i < 4; i++)
        #pragma unroll
        for (int j = 0; j < 4; j++) {
            float v0, v1;
            upk2(acc[i][j], v0, v1);
            int n = n0 + 2 * j;
            S.T1[r0 + i][n]     = silu(v0 + b1v[n]);
            S.T1[r0 + i][n + 1] = silu(v1 + b1v[n + 1]);
            acc[i][j] = 0ull;
        }
    __syncthreads();
    for (int kc = 0; kc < 128; kc += 32) {
        load_w_chunk(&S.Wt[0][0], W2 + kc * H, tid);
        __syncthreads();
        gemm_chunk(acc, &S.T1[r0][kc], &S.T1[r0 + 1][kc], &S.T1[r0 + 2][kc], &S.T1[r0 + 3][kc], &S.Wt[0][0], n0);
        __syncthreads();
    }
    #pragma unroll
    for (int i = 0; i < 4; i++) {
        int node = row0 + r0 + i;
        if (node < Nn) {
            #pragma unroll
            for (int j = 0; j < 4; j++) {
                float v0, v1;
                upk2(acc[i][j], v0, v1);
                int n = n0 + 2 * j;
                g_h1[(size_t)node * H + n]     = v0 + b2v[n]     + h[(size_t)node * H + n];
                g_h1[(size_t)node * H + n + 1] = v1 + b2v[n + 1] + h[(size_t)node * H + n + 1];
            }
        }
    }
}

// h2 = nodeMLP([mi, h1]);  xz = h2 @ in_proj_w ; split into g_x, g_z
__global__ __launch_bounds__(256, 3) void k_node2(
    const float* __restrict__ W1, const float* __restrict__ b1v,
    const float* __restrict__ W2, const float* __restrict__ b2v,
    const float* __restrict__ inpw, int Nn) {
    extern __shared__ char sraw[];
    SmemG& S = *(SmemG*)sraw;
    int tid = threadIdx.x;
    int row0 = blockIdx.x * 64;
    int tx = tid & 15, ty = tid >> 4;
    int n0 = tx * 8, r0 = ty * 4;
    int le = tid >> 2, lk = (tid & 3) * 8;
    int node_l = min(row0 + le, Nn - 1);
    ull acc[4][4] = {};
    for (int kc = 0; kc < 256; kc += 32) {
        const float* srcb = (kc < 128) ? g_mi : g_h1;
        const float* src = srcb + (size_t)node_l * H + (kc & 127) + lk;
        *(float4*)&S.At[le][lk]     = *(const float4*)src;
        *(float4*)&S.At[le][lk + 4] = *(const float4*)(src + 4);
        load_w_chunk(&S.Wt[0][0], W1 + kc * H, tid);
        __syncthreads();
        gemm_chunk(acc, &S.At[r0][0], &S.At[r0 + 1][0], &S.At[r0 + 2][0], &S.At[r0 + 3][0], &S.Wt[0][0], n0);
        __syncthreads();
    }
    #pragma unroll
    for (int i = 0; i < 4; i++)
        #pragma unroll
        for (int j = 0; j < 4; j++) {
            float v0, v1;
            upk2(acc[i][j], v0, v1);
            int n = n0 + 2 * j;
            S.T1[r0 + i][n]     = silu(v0 + b1v[n]);
            S.T1[r0 + i][n + 1] = silu(v1 + b1v[n + 1]);
            acc[i][j] = 0ull;
        }
    __syncthreads();
    for (int kc = 0; kc < 128; kc += 32) {
        load_w_chunk(&S.Wt[0][0], W2 + kc * H, tid);
        __syncthreads();
        gemm_chunk(acc, &S.T1[r0][kc], &S.T1[r0 + 1][kc], &S.T1[r0 + 2][kc], &S.T1[r0 + 3][kc], &S.Wt[0][0], n0);
        __syncthreads();
    }
    float h2v[4][8];
    #pragma unroll
    for (int i = 0; i < 4; i++)
        #pragma unroll
        for (int j = 0; j < 4; j++) {
            float v0, v1;
            upk2(acc[i][j], v0, v1);
            int n = n0 + 2 * j;
            h2v[i][2 * j] = v0 + b2v[n];
            h2v[i][2 * j + 1] = v1 + b2v[n + 1];
        }
    __syncthreads();
    #pragma unroll
    for (int i = 0; i < 4; i++)
        #pragma unroll
        for (int jj = 0; jj < 8; jj++) S.T1[r0 + i][n0 + jj] = h2v[i][jj];
    __syncthreads();
    for (int half = 0; half < 2; half++) {
        #pragma unroll
        for (int i = 0; i < 4; i++)
            #pragma unroll
            for (int j = 0; j < 4; j++) acc[i][j] = 0ull;
        for (int kc = 0; kc < 128; kc += 32) {
            load_w_chunk_strided(&S.Wt[0][0], inpw + kc * 256 + half * 128, 256, tid);
            __syncthreads();
            gemm_chunk(acc, &S.T1[r0][kc], &S.T1[r0 + 1][kc], &S.T1[r0 + 2][kc], &S.T1[r0 + 3][kc], &S.Wt[0][0], n0);
            __syncthreads();
        }
        float* dst = half ? g_z : g_x;
        #pragma unroll
        for (int i = 0; i < 4; i++) {
            int node = row0 + r0 + i;
            if (node < Nn) {
                #pragma unroll
                for (int j = 0; j < 4; j++) {
                    float v0, v1;
                    upk2(acc[i][j], v0, v1);
                    int n = n0 + 2 * j;
                    dst[(size_t)node * H + n] = v0;
                    dst[(size_t)node * H + n + 1] = v1;
                }
            }
        }
    }
}

// conv + silu -> xs ; B,C = xs @ x_proj_w[:,8:136] ; delta = softplus(xs @ M + dt_b)
__global__ __launch_bounds__(256, 3) void k_conv_proj(
    const float* __restrict__ xpw, const float* __restrict__ convw,
    const float* __restrict__ convb, const float* __restrict__ dtb, int Nn) {
    extern __shared__ char sraw[];
    SmemG& S = *(SmemG*)sraw;
    int tid = threadIdx.x;
    int row0 = blockIdx.x * 64;
    int tx = tid & 15, ty = tid >> 4;
    int n0 = tx * 8, r0 = ty * 4;
    for (int it = 0; it < 32; ++it) {
        int lin = it * 256 + tid;
        int r = lin >> 7, c = lin & 127;
        int node = row0 + r;
        float v = 0.f;
        if (node < Nn) {
            float a = convb[c];
            #pragma unroll
            for (int k = 0; k < 4; k++) {
                int t = node - 3 + k;
                if (t >= 0) a += convw[k * H + c] * g_x[(size_t)t * H + c];
            }
            v = silu(a);
            g_xs[(size_t)node * H + c] = v;
        }
        S.T1[r][c] = v;
    }
    __syncthreads();
    ull acc[4][4] = {};
    for (int kc = 0; kc < 128; kc += 32) {
        load_w_chunk_strided(&S.Wt[0][0], xpw + kc * 136 + 8, 136, tid);
        __syncthreads();
        gemm_chunk(acc, &S.T1[r0][kc], &S.T1[r0 + 1][kc], &S.T1[r0 + 2][kc], &S.T1[r0 + 3][kc], &S.Wt[0][0], n0);
        __syncthreads();
    }
    #pragma unroll
    for (int i = 0; i < 4; i++) {
        int node = row0 + r0 + i;
        if (node < Nn) {
            #pragma unroll
            for (int j = 0; j < 4; j++) {
                float v0, v1;
                upk2(acc[i][j], v0, v1);
                int n = n0 + 2 * j;
                if (n < 64) {
                    g_Bm[(size_t)node * DS + n] = v0;
                    g_Bm[(size_t)node * DS + n + 1] = v1;
                } else {
                    g_Cm[(size_t)node * DS + n - 64] = v0;
                    g_Cm[(size_t)node * DS + n - 63] = v1;
                }
            }
        }
        #pragma unroll
        for (int j = 0; j < 4; j++) acc[i][j] = 0ull;
    }
    for (int kc = 0; kc < 128; kc += 32) {
        load_w_chunk(&S.Wt[0][0], g_M + kc * H, tid);
        __syncthreads();
        gemm_chunk(acc, &S.T1[r0][kc], &S.T1[r0 + 1][kc], &S.T1[r0 + 2][kc], &S.T1[r0 + 3][kc], &S.Wt[0][0], n0);
        __syncthreads();
    }
    #pragma unroll
    for (int i = 0; i < 4; i++) {
        int node = row0 + r0 + i;
        if (node < Nn) {
            #pragma unroll
            for (int j = 0; j < 4; j++) {
                float v0, v1;
                upk2(acc[i][j], v0, v1);
                int n = n0 + 2 * j;
                g_delta[(size_t)node * H + n] = softplus(v0 + dtb[n]);
                g_delta[(size_t)node * H + n + 1] = softplus(v1 + dtb[n + 1]);
            }
        }
    }
}

// chunked selective scan, phase A: local scans per chunk
__global__ void k_scanA(const float* __restrict__ A_log, int Nn) {
    int warp = threadIdx.x >> 5;
    int lane = threadIdx.x & 31;
    int c = blockIdx.x;
    int hch = blockIdx.y * 8 + warp;
    int s0 = lane, s1 = lane + 32;
    float A0 = -__expf(A_log[hch * DS + s0]);
    float A1 = -__expf(A_log[hch * DS + s1]);
    float hc0 = 0.f, hc1 = 0.f, dsum = 0.f;
    int t0 = c * TCH, t1 = min(Nn, t0 + TCH);
    for (int t = t0; t < t1; ++t) {
        float d = __ldg(&g_delta[(size_t)t * H + hch]);
        float xv = __ldg(&g_xs[(size_t)t * H + hch]);
        float b0 = g_Bm[(size_t)t * DS + s0];
        float b1v = g_Bm[(size_t)t * DS + s1];
        float dx = d * xv;
        hc0 = __expf(d * A0) * hc0 + dx * b0;
        hc1 = __expf(d * A1) * hc1 + dx * b1v;
        dsum += d;
    }
    size_t o = ((size_t)c * H + hch) * DS;
    g_bstate[o + s0] = hc0;
    g_bstate[o + s1] = hc1;
    g_aprod[o + s0] = __expf(A0 * dsum);
    g_aprod[o + s1] = __expf(A1 * dsum);
}

// phase B: sequential prefix over chunks (8192 independent lanes)
__global__ void k_prefix(int NC) {
    int hs = blockIdx.x * blockDim.x + threadIdx.x;
    float st = 0.f;
    for (int c = 0; c < NC; c++) {
        size_t o = (size_t)c * (H * DS) + hs;
        g_sstart[o] = st;
        st = g_aprod[o] * st + g_bstate[o];
    }
}

// phase C: recompute within chunk, produce y (with +D*x and silu(z) gate)
__global__ void k_scanC(const float* __restrict__ A_log, const float* __restrict__ Dv, int Nn) {
    int warp = threadIdx.x >> 5;
    int lane = threadIdx.x & 31;
    int c = blockIdx.x;
    int hch = blockIdx.y * 8 + warp;
    int s0 = lane, s1 = lane + 32;
    float A0 = -__expf(A_log[hch * DS + s0]);
    float A1 = -__expf(A_log[hch * DS + s1]);
    size_t o = ((size_t)c * H + hch) * DS;
    float hc0 = g_sstart[o + s0];
    float hc1 = g_sstart[o + s1];
    float dh = Dv[hch];
    int t0 = c * TCH, t1 = min(Nn, t0 + TCH);
    for (int t = t0; t < t1; ++t) {
        float d = __ldg(&g_delta[(size_t)t * H + hch]);
        float xv = __ldg(&g_xs[(size_t)t * H + hch]);
        float b0 = g_Bm[(size_t)t * DS + s0];
        float b1v = g_Bm[(size_t)t * DS + s1];
        float c0 = g_Cm[(size_t)t * DS + s0];
        float c1 = g_Cm[(size_t)t * DS + s1];
        float dx = d * xv;
        hc0 = __expf(d * A0) * hc0 + dx * b0;
        hc1 = __expf(d * A1) * hc1 + dx * b1v;
        float p = hc0 * c0 + hc1 * c1;
        #pragma unroll
        for (int off = 16; off; off >>= 1) p += __shfl_down_sync(0xffffffffu, p, off);
        if (lane == 0) {
            float zv = g_z[(size_t)t * H + hch];
            g_y[(size_t)t * H + hch] = (p + dh * xv) * zv * sigm(zv);
        }
    }
}

// out = y @ out_proj_w
__global__ __launch_bounds__(256, 3) void k_out(const float* __restrict__ W, float* __restrict__ out, int Nn) {
    extern __shared__ char sraw[];
    SmemG& S = *(SmemG*)sraw;
    int tid = threadIdx.x;
    int row0 = blockIdx.x * 64;
    int tx = tid & 15, ty = tid >> 4;
    int n0 = tx * 8, r0 = ty * 4;
    for (int it = 0; it < 32; ++it) {
        int lin = it * 256 + tid;
        int r = lin >> 7, c = lin & 127;
        int node = min(row0 + r, Nn - 1);
        S.T1[r][c] = g_y[(size_t)node * H + c];
    }
    __syncthreads();
    ull acc[4][4] = {};
    for (int kc = 0; kc < 128; kc += 32) {
        load_w_chunk(&S.Wt[0][0], W + kc * H, tid);
        __syncthreads();
        gemm_chunk(acc, &S.T1[r0][kc], &S.T1[r0 + 1][kc], &S.T1[r0 + 2][kc], &S.T1[r0 + 3][kc], &S.Wt[0][0], n0);
        __syncthreads();
    }
    #pragma unroll
    for (int i = 0; i < 4; i++) {
        int node = row0 + r0 + i;
        if (node < Nn) {
            #pragma unroll
            for (int j = 0; j < 4; j++) {
                float v0, v1;
                upk2(acc[i][j], v0, v1);
                int n = n0 + 2 * j;
                out[(size_t)node * H + n] = v0;
                out[(size_t)node * H + n + 1] = v1;
            }
        }
    }
}

// ---------------- launch ----------------
extern "C" void kernel_launch(void* const* d_in, const int* in_sizes, int n_in,
                              void* d_out, int out_size) {
    const float* h      = (const float*)d_in[0];
    const void*  eidx   = d_in[1];
    const float* eattr  = (const float*)d_in[2];
    const float* e_w1   = (const float*)d_in[3];
    const float* e_b1   = (const float*)d_in[4];
    const float* e_w2   = (const float*)d_in[5];
    const float* e_b2   = (const float*)d_in[6];
    const float* inf_w  = (const float*)d_in[7];
    const float* inf_b  = (const float*)d_in[8];
    const float* n_w1   = (const float*)d_in[9];
    const float* n_b1   = (const float*)d_in[10];
    const float* n_w2   = (const float*)d_in[11];
    const float* n_b2   = (const float*)d_in[12];
    const float* in_prj = (const float*)d_in[13];
    const float* conv_w = (const float*)d_in[14];
    const float* conv_b = (const float*)d_in[15];
    const float* x_proj = (const float*)d_in[16];
    const float* dt_w   = (const float*)d_in[17];
    const float* dt_b   = (const float*)d_in[18];
    const float* A_log  = (const float*)d_in[19];
    const float* Dv     = (const float*)d_in[20];
    const float* out_w  = (const float*)d_in[21];

    int Nn = in_sizes[0] / H;
    int E  = in_sizes[2] / 2;
    int NC = (Nn + TCH - 1) / TCH;
    int nb = (Nn + 63) / 64;
    int smemG = (int)sizeof(SmemG);
    int smemE = (int)sizeof(SmemE);

    cudaFuncSetAttribute(k_pq,        cudaFuncAttributeMaxDynamicSharedMemorySize, smemG);
    cudaFuncSetAttribute(k_edge,      cudaFuncAttributeMaxDynamicSharedMemorySize, smemE);
    cudaFuncSetAttribute(k_node1,     cudaFuncAttributeMaxDynamicSharedMemorySize, smemG);
    cudaFuncSetAttribute(k_node2,     cudaFuncAttributeMaxDynamicSharedMemorySize, smemG);
    cudaFuncSetAttribute(k_conv_proj, cudaFuncAttributeMaxDynamicSharedMemorySize, smemG);
    cudaFuncSetAttribute(k_out,       cudaFuncAttributeMaxDynamicSharedMemorySize, smemG);

    k_detect<<<1, 32>>>((const int*)eidx);
    k_zero<<<256, 256>>>(Nn * H);
    k_premat<<<64, 256>>>(x_proj, dt_w);
    k_pq<<<nb, 256, smemG>>>(h, e_w1, Nn);
    k_edge<<<(E + 63) / 64, 256, smemE>>>(eidx, eattr, e_w1, e_b1, e_w2, e_b2, inf_w, inf_b, E);
    k_node1<<<nb, 256, smemG>>>(h, n_w1, n_b1, n_w2, n_b2, Nn);
    k_node2<<<nb, 256, smemG>>>(n_w1, n_b1, n_w2, n_b2, in_prj, Nn);
    k_conv_proj<<<nb, 256, smemG>>>(x_proj, conv_w, conv_b, dt_b, Nn);
    dim3 gs(NC, 16);
    k_scanA<<<gs, 256>>>(A_log, Nn);
    k_prefix<<<32, 256>>>(NC);
    k_scanC<<<gs, 256>>>(A_log, Dv, Nn);
    k_out<<<nb, 256, smemG>>>(out_w, (float*)d_out, Nn);
}

// round 3
// speedup vs baseline: 2.6857x; 1.6427x over previous
#include <cuda_runtime.h>
#include <math.h>

#define H 128
#define DS 64
#define TCH 128
#define MAXN 20000
#define MAXNC 157

typedef unsigned long long ull;

// ---------------- scratch (device globals; no allocations allowed) ----------------
__device__ float g_mi[MAXN * H];
__device__ float g_agg[MAXN * H];
__device__ float g_h1[MAXN * H];
__device__ float g_x[MAXN * H];
__device__ float g_z[MAXN * H];
__device__ float g_xs[MAXN * H];
__device__ float g_delta[MAXN * H];
__device__ float g_Bm[MAXN * DS];
__device__ float g_Cm[MAXN * DS];
__device__ float g_y[MAXN * H];
__device__ float g_P[MAXN * H];          // h @ W1a
__device__ float g_Q[MAXN * H];          // h @ W1b
__device__ float g_M[H * H];             // x_proj_w[:, :8] @ dt_w
__device__ float g_aprod[MAXNC * H * DS];
__device__ float g_bstate[MAXNC * H * DS];
__device__ float g_sstart[MAXNC * H * DS];
__device__ int   g_is64;

// ---------------- helpers ----------------
__device__ __forceinline__ float sigm(float v) { return 1.f / (1.f + __expf(-v)); }
__device__ __forceinline__ float silu(float v) { return v / (1.f + __expf(-v)); }
__device__ __forceinline__ float softplus(float v) { return (v > 20.f) ? v : log1pf(__expf(v)); }

__device__ __forceinline__ ull pk2(float a, float b) {
    ull r;
    asm("mov.b64 %0, {%1,%2};" : "=l"(r) : "f"(a), "f"(b));
    return r;
}
__device__ __forceinline__ void upk2(ull v, float& a, float& b) {
    asm("mov.b64 {%0,%1}, %2;" : "=f"(a), "=f"(b) : "l"(v));
}
// Blackwell packed fp32 FMA: 2 MACs per instruction
__device__ __forceinline__ void fma2(ull& d, ull a, ull b) {
    asm("fma.rn.f32x2 %0, %1, %2, %0;" : "+l"(d) : "l"(a), "l"(b));
}
// vector global reduction (sm_90+)
__device__ __forceinline__ void red4(float* p, float a, float b, float c, float d) {
    asm volatile("red.global.add.v4.f32 [%0], {%1,%2,%3,%4};"
                 :: "l"(p), "f"(a), "f"(b), "f"(c), "f"(d) : "memory");
}

// column ownership per thread: group0 = [c0, c0+4), group1 = [c0+64, c0+68), c0 = tx*4
// acc[i][0] -> cols c0,c0+1 ; acc[i][1] -> c0+2,c0+3 ; acc[i][2] -> c0+64,c0+65 ; acc[i][3] -> c0+66,c0+67

// shared tile layout for node-style kernels
struct SmemG {
    float At[64][36];
    float Wt[32][128];
    float T1[64][132];
    int   rs[64];
    int   cs[64];
    float ea[64][2];
};

// shared tile layout for edge kernel
struct SmemE {
    float T1[64][132];
    float Wt[32][128];
    int   rs[64];
    int   cs[64];
    float ea[64][2];
    float wc0[128];
    float wc1[128];
    float b1s[128];
};

__device__ __forceinline__ void load_w_chunk(float* wt, const float* __restrict__ src, int tid) {
    #pragma unroll
    for (int j = 0; j < 4; j++) {
        int li = j * 1024 + tid * 4;
        *(float4*)&wt[li] = *(const float4*)(src + li);
    }
}
__device__ __forceinline__ void load_w_chunk_strided(float* wt, const float* __restrict__ base, int ldg, int tid) {
    #pragma unroll
    for (int j = 0; j < 4; j++) {
        int li = j * 1024 + tid * 4;
        int row = li >> 7, col = li & 127;
        *(float4*)&wt[li] = *(const float4*)(base + row * ldg + col);
    }
}

// 32-step K-chunk: 4 rows x 8 cols per thread; conflict-free B access.
__device__ __forceinline__ void gemm_chunk(ull (&acc)[4][4],
                                           const float* a0, const float* a1,
                                           const float* a2, const float* a3,
                                           const float* wt, int c0) {
    #pragma unroll
    for (int kk = 0; kk < 32; kk += 4) {
        float4 A0 = *(const float4*)(a0 + kk);
        float4 A1 = *(const float4*)(a1 + kk);
        float4 A2 = *(const float4*)(a2 + kk);
        float4 A3 = *(const float4*)(a3 + kk);
        const float* w = wt + kk * 128 + c0;
        #pragma unroll
        for (int k4 = 0; k4 < 4; k4++) {
            ulonglong2 bA = *(const ulonglong2*)(w + k4 * 128);        // cols c0..c0+3
            ulonglong2 bB = *(const ulonglong2*)(w + k4 * 128 + 64);   // cols c0+64..c0+67
            float fa0 = (&A0.x)[k4], fa1 = (&A1.x)[k4];
            float fa2 = (&A2.x)[k4], fa3 = (&A3.x)[k4];
            ull p0 = pk2(fa0, fa0), p1 = pk2(fa1, fa1);
            ull p2 = pk2(fa2, fa2), p3 = pk2(fa3, fa3);
            fma2(acc[0][0], p0, bA.x); fma2(acc[0][1], p0, bA.y); fma2(acc[0][2], p0, bB.x); fma2(acc[0][3], p0, bB.y);
            fma2(acc[1][0], p1, bA.x); fma2(acc[1][1], p1, bA.y); fma2(acc[1][2], p1, bB.x); fma2(acc[1][3], p1, bB.y);
            fma2(acc[2][0], p2, bA.x); fma2(acc[2][1], p2, bA.y); fma2(acc[2][2], p2, bB.x); fma2(acc[2][3], p2, bB.y);
            fma2(acc[3][0], p3, bA.x); fma2(acc[3][1], p3, bA.y); fma2(acc[3][2], p3, bB.x); fma2(acc[3][3], p3, bB.y);
        }
    }
}

// unpack one row's accumulators into two float4 groups
__device__ __forceinline__ void unpack_row(const ull* accr, float4& g0, float4& g1) {
    upk2(accr[0], g0.x, g0.y);
    upk2(accr[1], g0.z, g0.w);
    upk2(accr[2], g1.x, g1.y);
    upk2(accr[3], g1.z, g1.w);
}

// ---------------- kernels ----------------
__global__ void k_detect(const int* __restrict__ p) {
    if (threadIdx.x == 0) {
        int nz = 0;
        for (int i = 1; i < 128; i += 2) nz += (p[i] != 0);
        g_is64 = (nz == 0) ? 1 : 0;
    }
}

__global__ void k_zero(int n) {
    for (int i = blockIdx.x * blockDim.x + threadIdx.x; i < n; i += gridDim.x * blockDim.x) {
        g_mi[i] = 0.f;
        g_agg[i] = 0.f;
    }
}

__global__ void k_premat(const float* __restrict__ xpw, const float* __restrict__ dtw) {
    int o = blockIdx.x * blockDim.x + threadIdx.x;
    int i = o >> 7, j = o & 127;
    float s = 0.f;
    #pragma unroll
    for (int r = 0; r < 8; r++) s += xpw[i * 136 + r] * dtw[r * 128 + j];
    g_M[o] = s;
}

// P = h @ W1[0:128], Q = h @ W1[128:256]
__global__ __launch_bounds__(256, 3) void k_pq(
    const float* __restrict__ h, const float* __restrict__ W1, int Nn) {
    extern __shared__ char sraw[];
    SmemG& S = *(SmemG*)sraw;
    int tid = threadIdx.x;
    int row0 = blockIdx.x * 64;
    int tx = tid & 15, ty = tid >> 4;
    int c0 = tx * 4, r0 = ty * 4;
    for (int it = 0; it < 32; ++it) {
        int lin = it * 256 + tid;
        int r = lin >> 7, c = lin & 127;
        int node = min(row0 + r, Nn - 1);
        S.T1[r][c] = h[(size_t)node * H + c];
    }
    __syncthreads();
    for (int tgt = 0; tgt < 2; tgt++) {
        ull acc[4][4] = {};
        for (int kc = 0; kc < 128; kc += 32) {
            load_w_chunk(&S.Wt[0][0], W1 + (tgt * 128 + kc) * H, tid);
            __syncthreads();
            gemm_chunk(acc, &S.T1[r0][kc], &S.T1[r0 + 1][kc], &S.T1[r0 + 2][kc], &S.T1[r0 + 3][kc], &S.Wt[0][0], c0);
            __syncthreads();
        }
        float* dst = tgt ? g_Q : g_P;
        #pragma unroll
        for (int i = 0; i < 4; i++) {
            int node = row0 + r0 + i;
            if (node < Nn) {
                float4 g0, g1;
                unpack_row(acc[i], g0, g1);
                *(float4*)(dst + (size_t)node * H + c0)      = g0;
                *(float4*)(dst + (size_t)node * H + c0 + 64) = g1;
            }
        }
    }
}

// Edge kernel: pre1 = P[row]+Q[col]+ea@W1c+b1 -> silu -> @W2+b2 -> silu = mij
// eij=sigmoid(mij.infw+infb); scatter mij->agg[row], mij*eij->mi[col]
__global__ __launch_bounds__(256, 3) void k_edge(
    const void* __restrict__ eidx, const float* __restrict__ eattr,
    const float* __restrict__ W1, const float* __restrict__ b1,
    const float* __restrict__ W2, const float* __restrict__ b2,
    const float* __restrict__ infw, const float* __restrict__ infb, int E) {
    extern __shared__ char sraw[];
    SmemE& S = *(SmemE*)sraw;
    int tid = threadIdx.x;
    int e0 = blockIdx.x * 64;
    int is64 = g_is64;
    if (tid < 64) {
        int e = min(e0 + tid, E - 1);
        if (is64) {
            const long long* q = (const long long*)eidx;
            S.rs[tid] = (int)q[e];
            S.cs[tid] = (int)q[(size_t)E + e];
        } else {
            const int* q = (const int*)eidx;
            S.rs[tid] = q[e];
            S.cs[tid] = q[E + e];
        }
        S.ea[tid][0] = eattr[2 * e];
        S.ea[tid][1] = eattr[2 * e + 1];
    }
    if (tid < 128) {
        S.wc0[tid] = W1[256 * H + tid];
        S.wc1[tid] = W1[257 * H + tid];
        S.b1s[tid] = b1[tid];
    }
    __syncthreads();

    // stage A: gather P[row] + Q[col], add ea terms + b1, silu -> T1
    {
        int r_loc = tid >> 3;          // 0..31
        int c8 = tid & 7;
        #pragma unroll
        for (int half = 0; half < 2; half++) {
            int r = half * 32 + r_loc;
            const float* Pr = g_P + (size_t)S.rs[r] * H;
            const float* Qr = g_Q + (size_t)S.cs[r] * H;
            float ea0 = S.ea[r][0], ea1 = S.ea[r][1];
            #pragma unroll
            for (int i = 0; i < 4; i++) {
                int c = c8 * 4 + i * 32;
                float4 p = *(const float4*)(Pr + c);
                float4 q = *(const float4*)(Qr + c);
                float4 o;
                #pragma unroll
                for (int j = 0; j < 4; j++) {
                    float v = (&p.x)[j] + (&q.x)[j]
                            + ea0 * S.wc0[c + j] + ea1 * S.wc1[c + j] + S.b1s[c + j];
                    (&o.x)[j] = silu(v);
                }
                *(float4*)&S.T1[r][c] = o;
            }
        }
    }
    __syncthreads();

    // stage B: K = 128 with W2
    int tx = tid & 15, ty = tid >> 4;
    int c0 = tx * 4, r0 = ty * 4;
    ull acc[4][4] = {};
    for (int kc = 0; kc < 128; kc += 32) {
        load_w_chunk(&S.Wt[0][0], W2 + kc * H, tid);
        __syncthreads();
        gemm_chunk(acc, &S.T1[r0][kc], &S.T1[r0 + 1][kc], &S.T1[r0 + 2][kc], &S.T1[r0 + 3][kc], &S.Wt[0][0], c0);
        __syncthreads();
    }
    float mv[4][8];
    #pragma unroll
    for (int i = 0; i < 4; i++) {
        float4 g0, g1;
        unpack_row(acc[i], g0, g1);
        #pragma unroll
        for (int j = 0; j < 4; j++) {
            mv[i][j]     = silu((&g0.x)[j] + b2[c0 + j]);
            mv[i][4 + j] = silu((&g1.x)[j] + b2[c0 + 64 + j]);
        }
    }
    // infiltration gate: per-edge dot(mij, infw), reduce over 16 threads sharing the edge
    float einf[4];
    #pragma unroll
    for (int i = 0; i < 4; i++) {
        float p = 0.f;
        #pragma unroll
        for (int j = 0; j < 4; j++) {
            p += mv[i][j] * __ldg(infw + c0 + j);
            p += mv[i][4 + j] * __ldg(infw + c0 + 64 + j);
        }
        #pragma unroll
        for (int off = 8; off; off >>= 1) p += __shfl_down_sync(0xffffffffu, p, off, 16);
        p = __shfl_sync(0xffffffffu, p, 0, 16);
        einf[i] = sigm(p + infb[0]);
    }
    // scatter via vector reductions
    #pragma unroll
    for (int i = 0; i < 4; i++) {
        if (e0 + r0 + i >= E) break;
        int er = S.rs[r0 + i], ec = S.cs[r0 + i];
        float g = einf[i];
        float* pa = g_agg + (size_t)er * H;
        float* pm = g_mi + (size_t)ec * H;
        red4(pa + c0,      mv[i][0], mv[i][1], mv[i][2], mv[i][3]);
        red4(pa + c0 + 64, mv[i][4], mv[i][5], mv[i][6], mv[i][7]);
        red4(pm + c0,      mv[i][0] * g, mv[i][1] * g, mv[i][2] * g, mv[i][3] * g);
        red4(pm + c0 + 64, mv[i][4] * g, mv[i][5] * g, mv[i][6] * g, mv[i][7] * g);
    }
}

// h1 = h + nodeMLP([h, agg])
__global__ __launch_bounds__(256, 3) void k_node1(
    const float* __restrict__ h,
    const float* __restrict__ W1, const float* __restrict__ b1v,
    const float* __restrict__ W2, const float* __restrict__ b2v, int Nn) {
    extern __shared__ char sraw[];
    SmemG& S = *(SmemG*)sraw;
    int tid = threadIdx.x;
    int row0 = blockIdx.x * 64;
    int tx = tid & 15, ty = tid >> 4;
    int c0 = tx * 4, r0 = ty * 4;
    int le = tid >> 2, lk = (tid & 3) * 8;
    int node_l = min(row0 + le, Nn - 1);
    ull acc[4][4] = {};
    for (int kc = 0; kc < 256; kc += 32) {
        const float* srcb = (kc < 128) ? h : g_agg;
        const float* src = srcb + (size_t)node_l * H + (kc & 127) + lk;
        *(float4*)&S.At[le][lk]     = *(const float4*)src;
        *(float4*)&S.At[le][lk + 4] = *(const float4*)(src + 4);
        load_w_chunk(&S.Wt[0][0], W1 + kc * H, tid);
        __syncthreads();
        gemm_chunk(acc, &S.At[r0][0], &S.At[r0 + 1][0], &S.At[r0 + 2][0], &S.At[r0 + 3][0], &S.Wt[0][0], c0);
        __syncthreads();
    }
    #pragma unroll
    for (int i = 0; i < 4; i++) {
        float4 g0, g1;
        unpack_row(acc[i], g0, g1);
        float4 s0, s1;
        #pragma unroll
        for (int j = 0; j < 4; j++) {
            (&s0.x)[j] = silu((&g0.x)[j] + b1v[c0 + j]);
            (&s1.x)[j] = silu((&g1.x)[j] + b1v[c0 + 64 + j]);
        }
        *(float4*)&S.T1[r0 + i][c0]      = s0;
        *(float4*)&S.T1[r0 + i][c0 + 64] = s1;
        #pragma unroll
        for (int j = 0; j < 4; j++) acc[i][j] = 0ull;
    }
    __syncthreads();
    for (int kc = 0; kc < 128; kc += 32) {
        load_w_chunk(&S.Wt[0][0], W2 + kc * H, tid);
        __syncthreads();
        gemm_chunk(acc, &S.T1[r0][kc], &S.T1[r0 + 1][kc], &S.T1[r0 + 2][kc], &S.T1[r0 + 3][kc], &S.Wt[0][0], c0);
        __syncthreads();
    }
    #pragma unroll
    for (int i = 0; i < 4; i++) {
        int node = row0 + r0 + i;
        if (node < Nn) {
            float4 g0, g1;
            unpack_row(acc[i], g0, g1);
            const float* hr = h + (size_t)node * H;
            float4 h0 = *(const float4*)(hr + c0);
            float4 h1 = *(const float4*)(hr + c0 + 64);
            float4 o0, o1;
            #pragma unroll
            for (int j = 0; j < 4; j++) {
                (&o0.x)[j] = (&g0.x)[j] + b2v[c0 + j]      + (&h0.x)[j];
                (&o1.x)[j] = (&g1.x)[j] + b2v[c0 + 64 + j] + (&h1.x)[j];
            }
            *(float4*)(g_h1 + (size_t)node * H + c0)      = o0;
            *(float4*)(g_h1 + (size_t)node * H + c0 + 64) = o1;
        }
    }
}

// h2 = nodeMLP([mi, h1]);  xz = h2 @ in_proj_w ; split into g_x, g_z
__global__ __launch_bounds__(256, 3) void k_node2(
    const float* __restrict__ W1, const float* __restrict__ b1v,
    const float* __restrict__ W2, const float* __restrict__ b2v,
    const float* __restrict__ inpw, int Nn) {
    extern __shared__ char sraw[];
    SmemG& S = *(SmemG*)sraw;
    int tid = threadIdx.x;
    int row0 = blockIdx.x * 64;
    int tx = tid & 15, ty = tid >> 4;
    int c0 = tx * 4, r0 = ty * 4;
    int le = tid >> 2, lk = (tid & 3) * 8;
    int node_l = min(row0 + le, Nn - 1);
    ull acc[4][4] = {};
    for (int kc = 0; kc < 256; kc += 32) {
        const float* srcb = (kc < 128) ? g_mi : g_h1;
        const float* src = srcb + (size_t)node_l * H + (kc & 127) + lk;
        *(float4*)&S.At[le][lk]     = *(const float4*)src;
        *(float4*)&S.At[le][lk + 4] = *(const float4*)(src + 4);
        load_w_chunk(&S.Wt[0][0], W1 + kc * H, tid);
        __syncthreads();
        gemm_chunk(acc, &S.At[r0][0], &S.At[r0 + 1][0], &S.At[r0 + 2][0], &S.At[r0 + 3][0], &S.Wt[0][0], c0);
        __syncthreads();
    }
    #pragma unroll
    for (int i = 0; i < 4; i++) {
        float4 g0, g1;
        unpack_row(acc[i], g0, g1);
        float4 s0, s1;
        #pragma unroll
        for (int j = 0; j < 4; j++) {
            (&s0.x)[j] = silu((&g0.x)[j] + b1v[c0 + j]);
            (&s1.x)[j] = silu((&g1.x)[j] + b1v[c0 + 64 + j]);
        }
        *(float4*)&S.T1[r0 + i][c0]      = s0;
        *(float4*)&S.T1[r0 + i][c0 + 64] = s1;
        #pragma unroll
        for (int j = 0; j < 4; j++) acc[i][j] = 0ull;
    }
    __syncthreads();
    for (int kc = 0; kc < 128; kc += 32) {
        load_w_chunk(&S.Wt[0][0], W2 + kc * H, tid);
        __syncthreads();
        gemm_chunk(acc, &S.T1[r0][kc], &S.T1[r0 + 1][kc], &S.T1[r0 + 2][kc], &S.T1[r0 + 3][kc], &S.Wt[0][0], c0);
        __syncthreads();
    }
    float h2v[4][8];
    #pragma unroll
    for (int i = 0; i < 4; i++) {
        float4 g0, g1;
        unpack_row(acc[i], g0, g1);
        #pragma unroll
        for (int j = 0; j < 4; j++) {
            h2v[i][j]     = (&g0.x)[j] + b2v[c0 + j];
            h2v[i][4 + j] = (&g1.x)[j] + b2v[c0 + 64 + j];
        }
    }
    __syncthreads();
    #pragma unroll
    for (int i = 0; i < 4; i++) {
        *(float4*)&S.T1[r0 + i][c0]      = *(float4*)&h2v[i][0];
        *(float4*)&S.T1[r0 + i][c0 + 64] = *(float4*)&h2v[i][4];
    }
    __syncthreads();
    for (int half = 0; half < 2; half++) {
        #pragma unroll
        for (int i = 0; i < 4; i++)
            #pragma unroll
            for (int j = 0; j < 4; j++) acc[i][j] = 0ull;
        for (int kc = 0; kc < 128; kc += 32) {
            load_w_chunk_strided(&S.Wt[0][0], inpw + kc * 256 + half * 128, 256, tid);
            __syncthreads();
            gemm_chunk(acc, &S.T1[r0][kc], &S.T1[r0 + 1][kc], &S.T1[r0 + 2][kc], &S.T1[r0 + 3][kc], &S.Wt[0][0], c0);
            __syncthreads();
        }
        float* dst = half ? g_z : g_x;
        #pragma unroll
        for (int i = 0; i < 4; i++) {
            int node = row0 + r0 + i;
            if (node < Nn) {
                float4 g0, g1;
                unpack_row(acc[i], g0, g1);
                *(float4*)(dst + (size_t)node * H + c0)      = g0;
                *(float4*)(dst + (size_t)node * H + c0 + 64) = g1;
            }
        }
    }
}

// conv + silu -> xs ; B,C = xs @ x_proj_w[:,8:136] ; delta = softplus(xs @ M + dt_b)
__global__ __launch_bounds__(256, 3) void k_conv_proj(
    const float* __restrict__ xpw, const float* __restrict__ convw,
    const float* __restrict__ convb, const float* __restrict__ dtb, int Nn) {
    extern __shared__ char sraw[];
    SmemG& S = *(SmemG*)sraw;
    int tid = threadIdx.x;
    int row0 = blockIdx.x * 64;
    int tx = tid & 15, ty = tid >> 4;
    int c0 = tx * 4, r0 = ty * 4;
    for (int it = 0; it < 32; ++it) {
        int lin = it * 256 + tid;
        int r = lin >> 7, c = lin & 127;
        int node = row0 + r;
        float v = 0.f;
        if (node < Nn) {
            float a = convb[c];
            #pragma unroll
            for (int k = 0; k < 4; k++) {
                int t = node - 3 + k;
                if (t >= 0) a += convw[k * H + c] * g_x[(size_t)t * H + c];
            }
            v = silu(a);
            g_xs[(size_t)node * H + c] = v;
        }
        S.T1[r][c] = v;
    }
    __syncthreads();
    ull acc[4][4] = {};
    for (int kc = 0; kc < 128; kc += 32) {
        load_w_chunk_strided(&S.Wt[0][0], xpw + kc * 136 + 8, 136, tid);
        __syncthreads();
        gemm_chunk(acc, &S.T1[r0][kc], &S.T1[r0 + 1][kc], &S.T1[r0 + 2][kc], &S.T1[r0 + 3][kc], &S.Wt[0][0], c0);
        __syncthreads();
    }
    #pragma unroll
    for (int i = 0; i < 4; i++) {
        int node = row0 + r0 + i;
        if (node < Nn) {
            float4 g0, g1;
            unpack_row(acc[i], g0, g1);
            *(float4*)(g_Bm + (size_t)node * DS + c0) = g0;   // cols c0..c0+3 (<64) -> B
            *(float4*)(g_Cm + (size_t)node * DS + c0) = g1;   // cols 64+c0..  -> C
        }
        #pragma unroll
        for (int j = 0; j < 4; j++) acc[i][j] = 0ull;
    }
    for (int kc = 0; kc < 128; kc += 32) {
        load_w_chunk(&S.Wt[0][0], g_M + kc * H, tid);
        __syncthreads();
        gemm_chunk(acc, &S.T1[r0][kc], &S.T1[r0 + 1][kc], &S.T1[r0 + 2][kc], &S.T1[r0 + 3][kc], &S.Wt[0][0], c0);
        __syncthreads();
    }
    #pragma unroll
    for (int i = 0; i < 4; i++) {
        int node = row0 + r0 + i;
        if (node < Nn) {
            float4 g0, g1;
            unpack_row(acc[i], g0, g1);
            float4 o0, o1;
            #pragma unroll
            for (int j = 0; j < 4; j++) {
                (&o0.x)[j] = softplus((&g0.x)[j] + dtb[c0 + j]);
                (&o1.x)[j] = softplus((&g1.x)[j] + dtb[c0 + 64 + j]);
            }
            *(float4*)(g_delta + (size_t)node * H + c0)      = o0;
            *(float4*)(g_delta + (size_t)node * H + c0 + 64) = o1;
        }
    }
}

// chunked selective scan, phase A: local scans per chunk
__global__ void k_scanA(const float* __restrict__ A_log, int Nn) {
    int warp = threadIdx.x >> 5;
    int lane = threadIdx.x & 31;
    int c = blockIdx.x;
    int hch = blockIdx.y * 8 + warp;
    int s0 = lane, s1 = lane + 32;
    float A0 = -__expf(A_log[hch * DS + s0]);
    float A1 = -__expf(A_log[hch * DS + s1]);
    float hc0 = 0.f, hc1 = 0.f, dsum = 0.f;
    int t0 = c * TCH, t1 = min(Nn, t0 + TCH);
    for (int t = t0; t < t1; ++t) {
        float d = __ldg(&g_delta[(size_t)t * H + hch]);
        float xv = __ldg(&g_xs[(size_t)t * H + hch]);
        float b0 = g_Bm[(size_t)t * DS + s0];
        float b1v = g_Bm[(size_t)t * DS + s1];
        float dx = d * xv;
        hc0 = __expf(d * A0) * hc0 + dx * b0;
        hc1 = __expf(d * A1) * hc1 + dx * b1v;
        dsum += d;
    }
    size_t o = ((size_t)c * H + hch) * DS;
    g_bstate[o + s0] = hc0;
    g_bstate[o + s1] = hc1;
    g_aprod[o + s0] = __expf(A0 * dsum);
    g_aprod[o + s1] = __expf(A1 * dsum);
}

// phase B: sequential prefix over chunks (8192 independent lanes)
__global__ void k_prefix(int NC) {
    int hs = blockIdx.x * blockDim.x + threadIdx.x;
    float st = 0.f;
    for (int c = 0; c < NC; c++) {
        size_t o = (size_t)c * (H * DS) + hs;
        g_sstart[o] = st;
        st = g_aprod[o] * st + g_bstate[o];
    }
}

// phase C: recompute within chunk, produce y (with +D*x and silu(z) gate)
__global__ void k_scanC(const float* __restrict__ A_log, const float* __restrict__ Dv, int Nn) {
    int warp = threadIdx.x >> 5;
    int lane = threadIdx.x & 31;
    int c = blockIdx.x;
    int hch = blockIdx.y * 8 + warp;
    int s0 = lane, s1 = lane + 32;
    float A0 = -__expf(A_log[hch * DS + s0]);
    float A1 = -__expf(A_log[hch * DS + s1]);
    size_t o = ((size_t)c * H + hch) * DS;
    float hc0 = g_sstart[o + s0];
    float hc1 = g_sstart[o + s1];
    float dh = Dv[hch];
    int t0 = c * TCH, t1 = min(Nn, t0 + TCH);
    for (int t = t0; t < t1; ++t) {
        float d = __ldg(&g_delta[(size_t)t * H + hch]);
        float xv = __ldg(&g_xs[(size_t)t * H + hch]);
        float b0 = g_Bm[(size_t)t * DS + s0];
        float b1v = g_Bm[(size_t)t * DS + s1];
        float c0 = g_Cm[(size_t)t * DS + s0];
        float c1 = g_Cm[(size_t)t * DS + s1];
        float dx = d * xv;
        hc0 = __expf(d * A0) * hc0 + dx * b0;
        hc1 = __expf(d * A1) * hc1 + dx * b1v;
        float p = hc0 * c0 + hc1 * c1;
        #pragma unroll
        for (int off = 16; off; off >>= 1) p += __shfl_down_sync(0xffffffffu, p, off);
        if (lane == 0) {
            float zv = g_z[(size_t)t * H + hch];
            g_y[(size_t)t * H + hch] = (p + dh * xv) * zv * sigm(zv);
        }
    }
}

// out = y @ out_proj_w
__global__ __launch_bounds__(256, 3) void k_out(const float* __restrict__ W, float* __restrict__ out, int Nn) {
    extern __shared__ char sraw[];
    SmemG& S = *(SmemG*)sraw;
    int tid = threadIdx.x;
    int row0 = blockIdx.x * 64;
    int tx = tid & 15, ty = tid >> 4;
    int c0 = tx * 4, r0 = ty * 4;
    for (int it = 0; it < 32; ++it) {
        int lin = it * 256 + tid;
        int r = lin >> 7, c = lin & 127;
        int node = min(row0 + r, Nn - 1);
        S.T1[r][c] = g_y[(size_t)node * H + c];
    }
    __syncthreads();
    ull acc[4][4] = {};
    for (int kc = 0; kc < 128; kc += 32) {
        load_w_chunk(&S.Wt[0][0], W + kc * H, tid);
        __syncthreads();
        gemm_chunk(acc, &S.T1[r0][kc], &S.T1[r0 + 1][kc], &S.T1[r0 + 2][kc], &S.T1[r0 + 3][kc], &S.Wt[0][0], c0);
        __syncthreads();
    }
    #pragma unroll
    for (int i = 0; i < 4; i++) {
        int node = row0 + r0 + i;
        if (node < Nn) {
            float4 g0, g1;
            unpack_row(acc[i], g0, g1);
            *(float4*)(out + (size_t)node * H + c0)      = g0;
            *(float4*)(out + (size_t)node * H + c0 + 64) = g1;
        }
    }
}

// ---------------- launch ----------------
extern "C" void kernel_launch(void* const* d_in, const int* in_sizes, int n_in,
                              void* d_out, int out_size) {
    const float* h      = (const float*)d_in[0];
    const void*  eidx   = d_in[1];
    const float* eattr  = (const float*)d_in[2];
    const float* e_w1   = (const float*)d_in[3];
    const float* e_b1   = (const float*)d_in[4];
    const float* e_w2   = (const float*)d_in[5];
    const float* e_b2   = (const float*)d_in[6];
    const float* inf_w  = (const float*)d_in[7];
    const float* inf_b  = (const float*)d_in[8];
    const float* n_w1   = (const float*)d_in[9];
    const float* n_b1   = (const float*)d_in[10];
    const float* n_w2   = (const float*)d_in[11];
    const float* n_b2   = (const float*)d_in[12];
    const float* in_prj = (const float*)d_in[13];
    const float* conv_w = (const float*)d_in[14];
    const float* conv_b = (const float*)d_in[15];
    const float* x_proj = (const float*)d_in[16];
    const float* dt_w   = (const float*)d_in[17];
    const float* dt_b   = (const float*)d_in[18];
    const float* A_log  = (const float*)d_in[19];
    const float* Dv     = (const float*)d_in[20];
    const float* out_w  = (const float*)d_in[21];

    int Nn = in_sizes[0] / H;
    int E  = in_sizes[2] / 2;
    int NC = (Nn + TCH - 1) / TCH;
    int nb = (Nn + 63) / 64;
    int smemG = (int)sizeof(SmemG);
    int smemE = (int)sizeof(SmemE);

    cudaFuncSetAttribute(k_pq,        cudaFuncAttributeMaxDynamicSharedMemorySize, smemG);
    cudaFuncSetAttribute(k_edge,      cudaFuncAttributeMaxDynamicSharedMemorySize, smemE);
    cudaFuncSetAttribute(k_node1,     cudaFuncAttributeMaxDynamicSharedMemorySize, smemG);
    cudaFuncSetAttribute(k_node2,     cudaFuncAttributeMaxDynamicSharedMemorySize, smemG);
    cudaFuncSetAttribute(k_conv_proj, cudaFuncAttributeMaxDynamicSharedMemorySize, smemG);
    cudaFuncSetAttribute(k_out,       cudaFuncAttributeMaxDynamicSharedMemorySize, smemG);

    k_detect<<<1, 32>>>((const int*)eidx);
    k_zero<<<256, 256>>>(Nn * H);
    k_premat<<<64, 256>>>(x_proj, dt_w);
    k_pq<<<nb, 256, smemG>>>(h, e_w1, Nn);
    k_edge<<<(E + 63) / 64, 256, smemE>>>(eidx, eattr, e_w1, e_b1, e_w2, e_b2, inf_w, inf_b, E);
    k_node1<<<nb, 256, smemG>>>(h, n_w1, n_b1, n_w2, n_b2, Nn);
    k_node2<<<nb, 256, smemG>>>(n_w1, n_b1, n_w2, n_b2, in_prj, Nn);
    k_conv_proj<<<nb, 256, smemG>>>(x_proj, conv_w, conv_b, dt_b, Nn);
    dim3 gs(NC, 16);
    k_scanA<<<gs, 256>>>(A_log, Nn);
    k_prefix<<<32, 256>>>(NC);
    k_scanC<<<gs, 256>>>(A_log, Dv, Nn);
    k_out<<<nb, 256, smemG>>>(out_w, (float*)d_out, Nn);
}